// round 15
// baseline (speedup 1.0000x reference)
#include <cuda_runtime.h>
#include <cuda_bf16.h>
#include <math.h>
#include <stdint.h>

// ---------------- problem dims ----------------
#define F_TOT 320
#define T_STEPS 20
#define B_SZ 16
#define CIN 64
#define CH 128
#define HW 1024
#define NT 2560            // total conv tiles (320 frames x 8 stripes)
#define GRID 148           // persistent CTAs

// conv smem layout
#define A_SPLIT 26112                  // 204 pixel-rows * 128B per split
#define B_BASE  78336                  // = 3 * A_SPLIT
#define B_OFF(b, s) (B_BASE + (b) * 49152 + (s) * 16384)
#define SCR_BASE 176640                // fp32 scratch [ci][py6][px], pitch 199 floats/ci
#define SCR_PITCH 199
#define CONV_SMEM (176640 + 50944)     // 227584 B

// ---------------- device scratch ----------------
__device__ __align__(16) __nv_bfloat16 g_b[3 * 9 * 128 * 64];      // [s][r][n][ci]
__device__ float g_y[(size_t)F_TOT * CH * HW];                     // 168 MB
__device__ float g_psum[F_TOT];
__device__ int   g_pmax[F_TOT];
__device__ float g_att[F_TOT];

__device__ __forceinline__ int enc_f(float v) {
    int ix = __float_as_int(v);
    return ix >= 0 ? ix : (ix ^ 0x7fffffff);
}
__device__ __forceinline__ float dec_f(int e) {
    int ix = e >= 0 ? e : (e ^ 0x7fffffff);
    return __int_as_float(ix);
}

__device__ __forceinline__ uint32_t smem_addr(const void* p) {
    uint32_t a;
    asm("{ .reg .u64 t; cvta.to.shared.u64 t, %1; cvt.u32.u64 %0, t; }" : "=r"(a) : "l"(p));
    return a;
}

#define CP16(dst, src) \
    asm volatile("cp.async.cg.shared.global [%0], [%1], 16;" :: "r"(dst), "l"(src))
#define CP4(dst, src) \
    asm volatile("cp.async.ca.shared.global [%0], [%1], 4;" :: "r"(dst), "l"(src))
#define CP_COMMIT() asm volatile("cp.async.commit_group;" ::: "memory")
#define CP_WAIT0()  asm volatile("cp.async.wait_group 0;" ::: "memory")

#define LDSM4(r0, r1, r2, r3, addr)                                              \
    asm volatile("ldmatrix.sync.aligned.m8n8.x4.shared.b16 {%0,%1,%2,%3}, [%4];" \
                 : "=r"(r0), "=r"(r1), "=r"(r2), "=r"(r3) : "r"(addr))

#define MMA16816(D, A, B0, B1)                                                 \
    asm volatile("mma.sync.aligned.m16n8k16.row.col.f32.bf16.bf16.f32 "        \
                 "{%0,%1,%2,%3}, {%4,%5,%6,%7}, {%8,%9}, {%0,%1,%2,%3};"       \
                 : "+f"(D[0]), "+f"(D[1]), "+f"(D[2]), "+f"(D[3])              \
                 : "r"(A[0]), "r"(A[1]), "r"(A[2]), "r"(A[3]), "r"(B0), "r"(B1))

__device__ __forceinline__ uint32_t pack_bf2(__nv_bfloat16 lo, __nv_bfloat16 hi) {
    return (uint32_t)__bfloat16_as_ushort(lo) | ((uint32_t)__bfloat16_as_ushort(hi) << 16);
}

// ---------------- kernel 1: reset pools ----------------
__global__ void init_kernel() {
    int i = blockIdx.x * blockDim.x + threadIdx.x;
    if (i < F_TOT) {
        g_psum[i] = 0.f;
        g_pmax[i] = 0x80000000;
    }
}

// ---------------- kernel 2: weight split-3 -> g_b[s][r][n][ci] ----------------
__global__ void prep_w_kernel(const float* __restrict__ w) {
    int i = blockIdx.x * blockDim.x + threadIdx.x;
    if (i >= 9 * 128 * 64) return;
    int r = i >> 13;
    int rem = i & 8191;
    int n = rem >> 6;
    int ci = rem & 63;
    float x = w[n * 576 + ci * 9 + r];
    __nv_bfloat16 b0 = __float2bfloat16(x);
    float r1 = x - __bfloat162float(b0);
    __nv_bfloat16 b1 = __float2bfloat16(r1);
    float r2 = r1 - __bfloat162float(b1);
    __nv_bfloat16 b2 = __float2bfloat16(r2);
    int off = r * 8192 + n * 64 + ci;
    g_b[off] = b0;
    g_b[73728 + off] = b1;
    g_b[2 * 73728 + off] = b2;
}

// ---------------- kernel 3: persistent mma.sync conv with inline split-3 ----------------
// grid = 148, 512 threads (16 warps)
// smem: [0, 78336) A tile (3 splits x 204 rows x 128B, swizzled)
//       [78336, 176640) B double buffer
//       [176640, 227584) fp32 scratch for next tile's raw rows
__global__ __launch_bounds__(512, 1) void conv_kernel(const float* __restrict__ data,
                                                      const float* __restrict__ bias) {
    extern __shared__ char smem[];
    const uint32_t sb = smem_addr(smem);
    __shared__ float red_s[16], red_m[16];

    const int tid = threadIdx.x;
    const int lane = tid & 31;
    const int wid = tid >> 5;
    const int warp_m = wid >> 2;      // 0..3 (32 pixels each)
    const int warp_n = wid & 3;       // 0..3 (32 channels each)

    // B staging map: row = tid>>2 (n 0..127), quarter = tid&3
    const int srow_i = tid >> 2;
    const int q = tid & 3;
    const uint32_t stgB_row = srow_i * 128;
    const uint32_t stgB_xor = (srow_i & 7) << 4;
    const uint32_t stgB_c0 = q * 32;

    // ldmatrix lane roles
    const uint32_t pbase = warp_m * 34 + (lane & 15);   // A pixel-row within padded tile
    const uint32_t cA = (lane >> 4) * 16;
    const uint32_t rowB_off = (warp_n * 32 + (lane & 7) + ((lane >> 4) & 1) * 8) * 128;
    const uint32_t cB = ((lane >> 3) & 1) * 16;
    const uint32_t xorB = (lane & 7) << 4;

    float acc_m[2][4][4];
    float acc_c[2][4][4];

    // fill scratch with raw fp32 rows for tile (f,row0): 64ci x 6py x 32px
    auto fill_scratch = [&](int f_, int row0_) {
        const float* fp = data + (size_t)f_ * 65536;
#pragma unroll
        for (int i = 0; i < 24; i++) {
            int e = tid + i * 512;           // < 12288
            int ci = e / 192;
            int rem = e - ci * 192;
            int py6 = rem >> 5;
            int px = rem & 31;
            int py = row0_ + py6 - 1;
            if ((unsigned)py < 32u) {
                uint32_t dst = sb + SCR_BASE + (uint32_t)(ci * SCR_PITCH + py6 * 33 + px) * 4;
                CP4(dst, fp + ci * 1024 + py * 32 + px);
            }
        }
    };

    // convert scratch -> swizzled A region (3 splits); formulas identical to prep
    auto convertA = [&](int row0_) {
#pragma unroll
        for (int i = 0; i < 4; i++) {
            int e = tid + i * 512;
            if (e < 1632) {
                int p = e >> 3;              // 0..203 pixel-row
                int g = e & 7;               // ci group
                int ci0 = g * 8;
                int prow = p / 34;
                int ppx = p - prow * 34;
                int py = row0_ + prow - 1;
                int pxm1 = ppx - 1;
                bool ok = ((unsigned)py < 32u) && ((unsigned)pxm1 < 32u);
                __nv_bfloat16 v0[8], v1[8], v2[8];
#pragma unroll
                for (int j = 0; j < 8; j++) {
                    float x = 0.f;
                    if (ok)
                        x = *(const float*)(smem + SCR_BASE +
                            (size_t)((ci0 + j) * SCR_PITCH + prow * 33 + pxm1) * 4);
                    __nv_bfloat16 b0 = __float2bfloat16(x);
                    float r1 = x - __bfloat162float(b0);
                    __nv_bfloat16 b1 = __float2bfloat16(r1);
                    float r2 = r1 - __bfloat162float(b1);
                    __nv_bfloat16 b2 = __float2bfloat16(r2);
                    v0[j] = b0; v1[j] = b1; v2[j] = b2;
                }
                uint32_t doff = p * 128 + ((g * 16) ^ ((p & 7) << 4));
                uint4 q0 = make_uint4(pack_bf2(v0[0], v0[1]), pack_bf2(v0[2], v0[3]),
                                      pack_bf2(v0[4], v0[5]), pack_bf2(v0[6], v0[7]));
                uint4 q1 = make_uint4(pack_bf2(v1[0], v1[1]), pack_bf2(v1[2], v1[3]),
                                      pack_bf2(v1[4], v1[5]), pack_bf2(v1[6], v1[7]));
                uint4 q2 = make_uint4(pack_bf2(v2[0], v2[1]), pack_bf2(v2[2], v2[3]),
                                      pack_bf2(v2[4], v2[5]), pack_bf2(v2[6], v2[7]));
                *(uint4*)(smem + 0 * A_SPLIT + doff) = q0;
                *(uint4*)(smem + 1 * A_SPLIT + doff) = q1;
                *(uint4*)(smem + 2 * A_SPLIT + doff) = q2;
            }
        }
    };

    auto stageB = [&](int r, int b) {
        const size_t bbase = (size_t)r * 8192 + (size_t)srow_i * 64 + q * 16;
#pragma unroll
        for (int s = 0; s < 3; s++) {
            const __nv_bfloat16* pb = g_b + bbase + (size_t)s * 73728;
            uint32_t db = sb + B_OFF(b, s) + stgB_row;
#pragma unroll
            for (int j = 0; j < 2; j++) {
                uint32_t sw = (stgB_c0 + j * 16) ^ stgB_xor;
                CP16(db + sw, pb + j * 8);
            }
        }
    };

    auto ldA = [&](int s, int droff, int k, uint32_t (&Af)[2][4]) {
#pragma unroll
        for (int mt = 0; mt < 2; mt++) {
            uint32_t p = pbase + droff + mt * 16;
            uint32_t addr = sb + s * A_SPLIT + p * 128 + ((cA + k * 32) ^ ((p & 7) << 4));
            LDSM4(Af[mt][0], Af[mt][1], Af[mt][2], Af[mt][3], addr);
        }
    };
    auto ldB = [&](uint32_t bb, int k, uint32_t (&Bf)[2][4]) {
#pragma unroll
        for (int bh = 0; bh < 2; bh++) {
            uint32_t addr = bb + rowB_off + bh * 2048 + ((cB + k * 32) ^ xorB);
            LDSM4(Bf[bh][0], Bf[bh][1], Bf[bh][2], Bf[bh][3], addr);
        }
    };
    auto mma8 = [&](uint32_t (&Af)[2][4], uint32_t (&Bf)[2][4], float (&acc)[2][4][4]) {
#pragma unroll
        for (int mt = 0; mt < 2; mt++)
#pragma unroll
            for (int nt = 0; nt < 4; nt++)
                MMA16816(acc[mt][nt], Af[mt], Bf[nt >> 1][(nt & 1) * 2],
                         Bf[nt >> 1][(nt & 1) * 2 + 1]);
    };
    auto compute = [&](int b, int droff) {
        const uint32_t b0 = sb + B_OFF(b, 0), b1 = sb + B_OFF(b, 1), b2 = sb + B_OFF(b, 2);
#pragma unroll
        for (int k = 0; k < 4; k++) {
            uint32_t Af0[2][4], Afx[2][4], Bf0[2][4], Bfx[2][4];
            ldA(0, droff, k, Af0);
            ldA(1, droff, k, Afx);
            ldB(b0, k, Bf0);
            ldB(b1, k, Bfx);
            mma8(Af0, Bf0, acc_m);   // main A0B0
            mma8(Afx, Bf0, acc_c);   // A1B0
            mma8(Afx, Bfx, acc_c);   // A1B1   (A1 dead after)
            ldA(2, droff, k, Afx);   // A2 -> Afx
            mma8(Af0, Bfx, acc_c);   // A0B1   (B1 dead after)
            ldB(b2, k, Bfx);         // B2 -> Bfx
            mma8(Afx, Bf0, acc_c);   // A2B0
            mma8(Af0, Bfx, acc_c);   // A0B2
        }
    };

    // ---- prologue: scratch + B(r=0) for first tile, then convert ----
    int buf = 0;
    {
        int t0 = blockIdx.x;
        fill_scratch(t0 >> 3, (t0 & 7) * 4);
        stageB(0, 0);
        CP_COMMIT();
        CP_WAIT0();
        __syncthreads();
        convertA((t0 & 7) * 4);
        // visibility of A STS handled by the r-loop-top __syncthreads
    }

    for (int tix = blockIdx.x; tix < NT; tix += GRID) {
        const int f = tix >> 3;
        const int row0 = (tix & 7) * 4;

#pragma unroll
        for (int i = 0; i < 2; i++)
#pragma unroll
            for (int j = 0; j < 4; j++)
#pragma unroll
                for (int d = 0; d < 4; d++) {
                    acc_m[i][j][d] = 0.f;
                    acc_c[i][j][d] = 0.f;
                }

        for (int r = 0; r < 9; r++) {
            CP_WAIT0();
            __syncthreads();          // publishes staged data (and convertA STS)
            if (r < 8) {
                stageB(r + 1, buf ^ 1);
                CP_COMMIT();
            }
            compute(buf, (r / 3) * 34 + (r % 3));
            buf ^= 1;
        }

        // ---- epilogue: prefetch raw rows + B(0) for next tile, store y, convert ----
        __syncthreads();              // all compute done; A/B/scratch free
        const int ntix = tix + GRID;
        const int nrow0 = (ntix & 7) * 4;
        if (ntix < NT) {
            fill_scratch(ntix >> 3, nrow0);
            stageB(0, buf);
            CP_COMMIT();
        }

        // direct-register epilogue: bias + store + pool
        float lsum = 0.f, lmax = -1e30f;
        const size_t yb = (size_t)f * (CH * HW) + (size_t)row0 * 32;
#pragma unroll
        for (int nt = 0; nt < 4; nt++) {
            const int n0 = warp_n * 32 + nt * 8 + 2 * (lane & 3);
            const float bv0 = __ldg(&bias[n0]);
            const float bv1 = __ldg(&bias[n0 + 1]);
            const size_t cb0 = yb + (size_t)n0 * HW;
            const size_t cb1 = yb + (size_t)(n0 + 1) * HW;
#pragma unroll
            for (int mt = 0; mt < 2; mt++) {
                const int m0 = warp_m * 32 + mt * 16 + (lane >> 2);
                float v0 = acc_m[mt][nt][0] + acc_c[mt][nt][0] + bv0;
                float v1 = acc_m[mt][nt][1] + acc_c[mt][nt][1] + bv1;
                float v2 = acc_m[mt][nt][2] + acc_c[mt][nt][2] + bv0;
                float v3 = acc_m[mt][nt][3] + acc_c[mt][nt][3] + bv1;
                g_y[cb0 + m0]     = v0;
                g_y[cb1 + m0]     = v1;
                g_y[cb0 + m0 + 8] = v2;
                g_y[cb1 + m0 + 8] = v3;
                lsum += v0 + v1 + v2 + v3;
                lmax = fmaxf(lmax, fmaxf(fmaxf(v0, v1), fmaxf(v2, v3)));
            }
        }

#pragma unroll
        for (int off = 16; off; off >>= 1) {
            lsum += __shfl_down_sync(0xffffffff, lsum, off);
            lmax = fmaxf(lmax, __shfl_down_sync(0xffffffff, lmax, off));
        }
        if (lane == 0) {
            red_s[wid] = lsum;
            red_m[wid] = lmax;
        }
        __syncthreads();
        if (tid == 0) {
            float s = 0.f, mx = -1e30f;
#pragma unroll
            for (int w = 0; w < 16; w++) {
                s += red_s[w];
                mx = fmaxf(mx, red_m[w]);
            }
            atomicAdd(&g_psum[f], s);
            atomicMax(&g_pmax[f], enc_f(mx));
        }

        if (ntix < NT) {
            CP_WAIT0();               // scratch + B(0) cps done (this thread)
            __syncthreads();          // all threads' scratch visible
            convertA(nrow0);          // STS -> A region; visible after r0-top sync
        }
    }
}

// ---------------- kernel 4: temporal attention ----------------
__global__ void att_kernel(const float* __restrict__ w1, const float* __restrict__ w2) {
    int tid = threadIdx.x;
    if (tid >= F_TOT) return;
    int b = tid / T_STEPS;
    int t = tid - b * T_STEPS;
    float avgv[T_STEPS], mxv[T_STEPS];
#pragma unroll
    for (int tt = 0; tt < T_STEPS; tt++) {
        avgv[tt] = g_psum[b * T_STEPS + tt] * (1.f / (float)(CH * HW));
        mxv[tt] = dec_f(g_pmax[b * T_STEPS + tt]);
    }
    float o = 0.f;
#pragma unroll
    for (int j = 0; j < 5; j++) {
        float ha = 0.f, hm = 0.f;
#pragma unroll
        for (int tt = 0; tt < T_STEPS; tt++) {
            float w = w1[j * T_STEPS + tt];
            ha = fmaf(avgv[tt], w, ha);
            hm = fmaf(mxv[tt], w, hm);
        }
        ha = fmaxf(ha, 0.f);
        hm = fmaxf(hm, 0.f);
        o = fmaf(ha + hm, w2[t * 5 + j], o);
    }
    g_att[tid] = 1.f / (1.f + expf(-o));
}

// ---------------- kernel 5: LIF ----------------
__global__ __launch_bounds__(256) void lif_kernel(float* __restrict__ out) {
    int idx = blockIdx.x * blockDim.x + threadIdx.x;
    int b = idx >> 17;
    int r = idx & 131071;
    float h = 0.f;
#pragma unroll
    for (int t = 0; t < T_STEPS; t++) {
        int f = b * T_STEPS + t;
        size_t off = (size_t)f * (CH * HW) + r;
        float v = g_y[off] * g_att[f];
        float u = fmaf(h, 0.3f, v);
        float s = (u >= 0.6f) ? 1.f : 0.f;
        out[off] = s;
        h = u * (1.f - s);
    }
}

// ---------------- launch ----------------
extern "C" void kernel_launch(void* const* d_in, const int* in_sizes, int n_in,
                              void* d_out, int out_size) {
    const float* data   = (const float*)d_in[0];
    const float* conv_w = (const float*)d_in[1];
    const float* conv_b = (const float*)d_in[2];
    const float* mlp_w1 = (const float*)d_in[3];
    const float* mlp_w2 = (const float*)d_in[4];
    float* out = (float*)d_out;

    static int smem_set = 0;
    if (!smem_set) {
        cudaFuncSetAttribute(conv_kernel, cudaFuncAttributeMaxDynamicSharedMemorySize,
                             CONV_SMEM);
        smem_set = 1;
    }

    init_kernel<<<(F_TOT + 255) / 256, 256>>>();
    prep_w_kernel<<<(9 * 128 * 64 + 255) / 256, 256>>>(conv_w);
    conv_kernel<<<GRID, 512, CONV_SMEM>>>(data, conv_b);
    att_kernel<<<1, F_TOT>>>(mlp_w1, mlp_w2);
    lif_kernel<<<(B_SZ * CH * HW) / 256, 256>>>(out);
}

// round 17
// speedup vs baseline: 1.0527x; 1.0527x over previous
#include <cuda_runtime.h>
#include <cuda_bf16.h>
#include <math.h>
#include <stdint.h>

// ---------------- problem dims ----------------
#define F_TOT 320
#define T_STEPS 20
#define B_SZ 16
#define CIN 64
#define CH 128
#define HW 1024
#define NT 2560            // total conv tiles (320 frames x 8 stripes)
#define GRID 148           // persistent CTAs

// padded plane strides (bf16 elements): [f][split][py34][px34][ci]
#define PL_PX 64
#define PL_PY 2176                     // 34*64
#define PL_S  73984                    // 34*2176
#define PL_F  221952                   // 3*PL_S

// conv smem layout
#define A_SPLIT 26112                  // 204 pixel-rows * 128B per split
#define B_BASE  78336                  // = 3 * A_SPLIT
#define B_OFF(b, s) (B_BASE + (b) * 49152 + (s) * 16384)
#define CONV_SMEM (78336 + 98304)      // 176640 B

// ---------------- device scratch ----------------
__device__ __align__(16) __nv_bfloat16 g_a[(size_t)F_TOT * PL_F];  // 142 MB
__device__ __align__(16) __nv_bfloat16 g_b[3 * 9 * 128 * 64];      // [s][r][n][ci]
__device__ float g_y[(size_t)F_TOT * CH * HW];                     // 168 MB
__device__ float g_psum[F_TOT];
__device__ int   g_pmax[F_TOT];
__device__ float g_att[F_TOT];

__device__ __forceinline__ int enc_f(float v) {
    int ix = __float_as_int(v);
    return ix >= 0 ? ix : (ix ^ 0x7fffffff);
}
__device__ __forceinline__ float dec_f(int e) {
    int ix = e >= 0 ? e : (e ^ 0x7fffffff);
    return __int_as_float(ix);
}

__device__ __forceinline__ uint32_t smem_addr(const void* p) {
    uint32_t a;
    asm("{ .reg .u64 t; cvta.to.shared.u64 t, %1; cvt.u32.u64 %0, t; }" : "=r"(a) : "l"(p));
    return a;
}

#define CP16(dst, src) \
    asm volatile("cp.async.cg.shared.global [%0], [%1], 16;" :: "r"(dst), "l"(src))
#define CP_COMMIT() asm volatile("cp.async.commit_group;" ::: "memory")
#define CP_WAIT0()  asm volatile("cp.async.wait_group 0;" ::: "memory")

#define LDSM4(r0, r1, r2, r3, addr)                                              \
    asm volatile("ldmatrix.sync.aligned.m8n8.x4.shared.b16 {%0,%1,%2,%3}, [%4];" \
                 : "=r"(r0), "=r"(r1), "=r"(r2), "=r"(r3) : "r"(addr))

#define MMA16816(D, A, B0, B1)                                                 \
    asm volatile("mma.sync.aligned.m16n8k16.row.col.f32.bf16.bf16.f32 "        \
                 "{%0,%1,%2,%3}, {%4,%5,%6,%7}, {%8,%9}, {%0,%1,%2,%3};"       \
                 : "+f"(D[0]), "+f"(D[1]), "+f"(D[2]), "+f"(D[3])              \
                 : "r"(A[0]), "r"(A[1]), "r"(A[2]), "r"(A[3]), "r"(B0), "r"(B1))

__device__ __forceinline__ uint32_t pack_bf2(__nv_bfloat16 lo, __nv_bfloat16 hi) {
    return (uint32_t)__bfloat16_as_ushort(lo) | ((uint32_t)__bfloat16_as_ushort(hi) << 16);
}

// ---------------- kernel 1: weight split-3 + pool init ----------------
__global__ void prep_w_kernel(const float* __restrict__ w) {
    int i = blockIdx.x * blockDim.x + threadIdx.x;
    if (i < F_TOT) {                 // fold pool init into this launch
        g_psum[i] = 0.f;
        g_pmax[i] = 0x80000000;
    }
    if (i >= 9 * 128 * 64) return;
    int r = i >> 13;
    int rem = i & 8191;
    int n = rem >> 6;
    int ci = rem & 63;
    float x = w[n * 576 + ci * 9 + r];
    __nv_bfloat16 b0 = __float2bfloat16(x);
    float r1 = x - __bfloat162float(b0);
    __nv_bfloat16 b1 = __float2bfloat16(r1);
    float r2 = r1 - __bfloat162float(b1);
    __nv_bfloat16 b2 = __float2bfloat16(r2);
    int off = r * 8192 + n * 64 + ci;
    g_b[off] = b0;
    g_b[73728 + off] = b1;
    g_b[2 * 73728 + off] = b2;
}

// ---------------- kernel 2: data split-3 -> zero-padded planes (vectorized) ----------------
// grid = (34 py34-rows, 320 frames), 256 threads
__global__ __launch_bounds__(256) void prep_data_kernel(const float* __restrict__ data) {
    __shared__ float srow[64][33];
    const int py34 = blockIdx.x;
    const int f = blockIdx.y;
    const int tid = threadIdx.x;
    const int py = py34 - 1;
    const bool rv = (unsigned)py < 32u;

    for (int e = tid; e < 2048; e += 256) {
        int ci = e >> 5, px = e & 31;
        srow[ci][px] = rv ? __ldg(&data[(size_t)f * 65536 + ci * 1024 + py * 32 + px]) : 0.f;
    }
    __syncthreads();

    const size_t rowbase = (size_t)f * PL_F + (size_t)py34 * PL_PY;
    // 34 px34 x 8 ci-groups = 272 work items; each produces 3 x uint4 (8 bf16 each)
#pragma unroll
    for (int e = tid; e < 272; e += 256) {
        int px34 = e >> 3;
        int g = e & 7;
        int ci0 = g * 8;
        int pxm1 = px34 - 1;
        bool ok = rv && (unsigned)pxm1 < 32u;
        __nv_bfloat16 v0[8], v1[8], v2[8];
#pragma unroll
        for (int j = 0; j < 8; j++) {
            float x = ok ? srow[ci0 + j][pxm1] : 0.f;
            __nv_bfloat16 b0 = __float2bfloat16(x);
            float r1 = x - __bfloat162float(b0);
            __nv_bfloat16 b1 = __float2bfloat16(r1);
            float r2 = r1 - __bfloat162float(b1);
            __nv_bfloat16 b2 = __float2bfloat16(r2);
            v0[j] = b0; v1[j] = b1; v2[j] = b2;
        }
        size_t o = rowbase + (size_t)px34 * PL_PX + ci0;
        *(uint4*)&g_a[o] = make_uint4(pack_bf2(v0[0], v0[1]), pack_bf2(v0[2], v0[3]),
                                      pack_bf2(v0[4], v0[5]), pack_bf2(v0[6], v0[7]));
        *(uint4*)&g_a[o + PL_S] = make_uint4(pack_bf2(v1[0], v1[1]), pack_bf2(v1[2], v1[3]),
                                             pack_bf2(v1[4], v1[5]), pack_bf2(v1[6], v1[7]));
        *(uint4*)&g_a[o + 2 * PL_S] = make_uint4(pack_bf2(v2[0], v2[1]), pack_bf2(v2[2], v2[3]),
                                                 pack_bf2(v2[4], v2[5]), pack_bf2(v2[6], v2[7]));
    }
}

// ---------------- kernel 3: persistent mma.sync conv (R11-identical) ----------------
__global__ __launch_bounds__(512, 1) void conv_kernel(const float* __restrict__ bias) {
    extern __shared__ char smem[];
    const uint32_t sb = smem_addr(smem);
    __shared__ float red_s[16], red_m[16];

    const int tid = threadIdx.x;
    const int lane = tid & 31;
    const int wid = tid >> 5;
    const int warp_m = wid >> 2;      // 0..3 (32 pixels each)
    const int warp_n = wid & 3;       // 0..3 (32 channels each)

    const int srow_i = tid >> 2;
    const int q = tid & 3;
    const uint32_t stgB_row = srow_i * 128;
    const uint32_t stgB_xor = (srow_i & 7) << 4;
    const uint32_t stgB_c0 = q * 32;

    const uint32_t pbase = warp_m * 34 + (lane & 15);
    const uint32_t cA = (lane >> 4) * 16;
    const uint32_t rowB_off = (warp_n * 32 + (lane & 7) + ((lane >> 4) & 1) * 8) * 128;
    const uint32_t cB = ((lane >> 3) & 1) * 16;
    const uint32_t xorB = (lane & 7) << 4;

    float acc_m[2][4][4];
    float acc_c[2][4][4];

    auto stageA = [&](int f_, int row0_) {
        const size_t fb = (size_t)f_ * PL_F;
        for (int e = tid; e < 4896; e += 512) {
            int s = e / 1632;
            int rem = e - s * 1632;
            int p = rem >> 3;
            int j = rem & 7;
            int prow = p / 34;
            int ppx = p - prow * 34;
            const __nv_bfloat16* src = g_a + fb + (size_t)s * PL_S +
                (size_t)(row0_ + prow) * PL_PY + ppx * PL_PX + j * 8;
            uint32_t dst = sb + s * A_SPLIT + p * 128 + ((j * 16) ^ ((p & 7) << 4));
            CP16(dst, src);
        }
    };

    auto stageB = [&](int r, int b) {
        const size_t bbase = (size_t)r * 8192 + (size_t)srow_i * 64 + q * 16;
#pragma unroll
        for (int s = 0; s < 3; s++) {
            const __nv_bfloat16* pb = g_b + bbase + (size_t)s * 73728;
            uint32_t db = sb + B_OFF(b, s) + stgB_row;
#pragma unroll
            for (int j = 0; j < 2; j++) {
                uint32_t sw = (stgB_c0 + j * 16) ^ stgB_xor;
                CP16(db + sw, pb + j * 8);
            }
        }
    };

    auto ldA = [&](int s, int droff, int k, uint32_t (&Af)[2][4]) {
#pragma unroll
        for (int mt = 0; mt < 2; mt++) {
            uint32_t p = pbase + droff + mt * 16;
            uint32_t addr = sb + s * A_SPLIT + p * 128 + ((cA + k * 32) ^ ((p & 7) << 4));
            LDSM4(Af[mt][0], Af[mt][1], Af[mt][2], Af[mt][3], addr);
        }
    };
    auto ldB = [&](uint32_t bb, int k, uint32_t (&Bf)[2][4]) {
#pragma unroll
        for (int bh = 0; bh < 2; bh++) {
            uint32_t addr = bb + rowB_off + bh * 2048 + ((cB + k * 32) ^ xorB);
            LDSM4(Bf[bh][0], Bf[bh][1], Bf[bh][2], Bf[bh][3], addr);
        }
    };
    auto mma8 = [&](uint32_t (&Af)[2][4], uint32_t (&Bf)[2][4], float (&acc)[2][4][4]) {
#pragma unroll
        for (int mt = 0; mt < 2; mt++)
#pragma unroll
            for (int nt = 0; nt < 4; nt++)
                MMA16816(acc[mt][nt], Af[mt], Bf[nt >> 1][(nt & 1) * 2],
                         Bf[nt >> 1][(nt & 1) * 2 + 1]);
    };
    auto compute = [&](int b, int droff) {
        const uint32_t b0 = sb + B_OFF(b, 0), b1 = sb + B_OFF(b, 1), b2 = sb + B_OFF(b, 2);
#pragma unroll
        for (int k = 0; k < 4; k++) {
            uint32_t Af0[2][4], Afx[2][4], Bf0[2][4], Bfx[2][4];
            ldA(0, droff, k, Af0);
            ldA(1, droff, k, Afx);
            ldB(b0, k, Bf0);
            ldB(b1, k, Bfx);
            mma8(Af0, Bf0, acc_m);   // main A0B0
            mma8(Afx, Bf0, acc_c);   // A1B0
            mma8(Afx, Bfx, acc_c);   // A1B1
            ldA(2, droff, k, Afx);
            mma8(Af0, Bfx, acc_c);   // A0B1
            ldB(b2, k, Bfx);
            mma8(Afx, Bf0, acc_c);   // A2B0
            mma8(Af0, Bfx, acc_c);   // A0B2
        }
    };

    int buf = 0;
    {
        int t0 = blockIdx.x;
        stageA(t0 >> 3, (t0 & 7) * 4);
        stageB(0, 0);
        CP_COMMIT();
    }

    for (int tix = blockIdx.x; tix < NT; tix += GRID) {
        const int f = tix >> 3;
        const int row0 = (tix & 7) * 4;

#pragma unroll
        for (int i = 0; i < 2; i++)
#pragma unroll
            for (int j = 0; j < 4; j++)
#pragma unroll
                for (int d = 0; d < 4; d++) {
                    acc_m[i][j][d] = 0.f;
                    acc_c[i][j][d] = 0.f;
                }

        for (int r = 0; r < 9; r++) {
            CP_WAIT0();
            __syncthreads();
            if (r < 8) {
                stageB(r + 1, buf ^ 1);
                CP_COMMIT();
            }
            compute(buf, (r / 3) * 34 + (r % 3));
            buf ^= 1;
        }

        __syncthreads();
        const int ntix = tix + GRID;
        if (ntix < NT) {
            stageA(ntix >> 3, (ntix & 7) * 4);
            stageB(0, buf);
            CP_COMMIT();
        }

        float lsum = 0.f, lmax = -1e30f;
        const size_t yb = (size_t)f * (CH * HW) + (size_t)row0 * 32;
#pragma unroll
        for (int nt = 0; nt < 4; nt++) {
            const int n0 = warp_n * 32 + nt * 8 + 2 * (lane & 3);
            const float bv0 = __ldg(&bias[n0]);
            const float bv1 = __ldg(&bias[n0 + 1]);
            const size_t cb0 = yb + (size_t)n0 * HW;
            const size_t cb1 = yb + (size_t)(n0 + 1) * HW;
#pragma unroll
            for (int mt = 0; mt < 2; mt++) {
                const int m0 = warp_m * 32 + mt * 16 + (lane >> 2);
                float v0 = acc_m[mt][nt][0] + acc_c[mt][nt][0] + bv0;
                float v1 = acc_m[mt][nt][1] + acc_c[mt][nt][1] + bv1;
                float v2 = acc_m[mt][nt][2] + acc_c[mt][nt][2] + bv0;
                float v3 = acc_m[mt][nt][3] + acc_c[mt][nt][3] + bv1;
                g_y[cb0 + m0]     = v0;
                g_y[cb1 + m0]     = v1;
                g_y[cb0 + m0 + 8] = v2;
                g_y[cb1 + m0 + 8] = v3;
                lsum += v0 + v1 + v2 + v3;
                lmax = fmaxf(lmax, fmaxf(fmaxf(v0, v1), fmaxf(v2, v3)));
            }
        }

#pragma unroll
        for (int off = 16; off; off >>= 1) {
            lsum += __shfl_down_sync(0xffffffff, lsum, off);
            lmax = fmaxf(lmax, __shfl_down_sync(0xffffffff, lmax, off));
        }
        if (lane == 0) {
            red_s[wid] = lsum;
            red_m[wid] = lmax;
        }
        __syncthreads();
        if (tid == 0) {
            float s = 0.f, mx = -1e30f;
#pragma unroll
            for (int w = 0; w < 16; w++) {
                s += red_s[w];
                mx = fmaxf(mx, red_m[w]);
            }
            atomicAdd(&g_psum[f], s);
            atomicMax(&g_pmax[f], enc_f(mx));
        }
    }
}

// ---------------- kernel 4: temporal attention ----------------
__global__ void att_kernel(const float* __restrict__ w1, const float* __restrict__ w2) {
    int tid = threadIdx.x;
    if (tid >= F_TOT) return;
    int b = tid / T_STEPS;
    int t = tid - b * T_STEPS;
    float avgv[T_STEPS], mxv[T_STEPS];
#pragma unroll
    for (int tt = 0; tt < T_STEPS; tt++) {
        avgv[tt] = g_psum[b * T_STEPS + tt] * (1.f / (float)(CH * HW));
        mxv[tt] = dec_f(g_pmax[b * T_STEPS + tt]);
    }
    float o = 0.f;
#pragma unroll
    for (int j = 0; j < 5; j++) {
        float ha = 0.f, hm = 0.f;
#pragma unroll
        for (int tt = 0; tt < T_STEPS; tt++) {
            float w = w1[j * T_STEPS + tt];
            ha = fmaf(avgv[tt], w, ha);
            hm = fmaf(mxv[tt], w, hm);
        }
        ha = fmaxf(ha, 0.f);
        hm = fmaxf(hm, 0.f);
        o = fmaf(ha + hm, w2[t * 5 + j], o);
    }
    g_att[tid] = 1.f / (1.f + expf(-o));
}

// ---------------- kernel 5: LIF ----------------
__global__ __launch_bounds__(256) void lif_kernel(float* __restrict__ out) {
    int idx = blockIdx.x * blockDim.x + threadIdx.x;
    int b = idx >> 17;
    int r = idx & 131071;
    float h = 0.f;
#pragma unroll
    for (int t = 0; t < T_STEPS; t++) {
        int f = b * T_STEPS + t;
        size_t off = (size_t)f * (CH * HW) + r;
        float v = g_y[off] * g_att[f];
        float u = fmaf(h, 0.3f, v);
        float s = (u >= 0.6f) ? 1.f : 0.f;
        out[off] = s;
        h = u * (1.f - s);
    }
}

// ---------------- launch ----------------
extern "C" void kernel_launch(void* const* d_in, const int* in_sizes, int n_in,
                              void* d_out, int out_size) {
    const float* data   = (const float*)d_in[0];
    const float* conv_w = (const float*)d_in[1];
    const float* conv_b = (const float*)d_in[2];
    const float* mlp_w1 = (const float*)d_in[3];
    const float* mlp_w2 = (const float*)d_in[4];
    float* out = (float*)d_out;

    static int smem_set = 0;
    if (!smem_set) {
        cudaFuncSetAttribute(conv_kernel, cudaFuncAttributeMaxDynamicSharedMemorySize,
                             CONV_SMEM);
        smem_set = 1;
    }

    prep_w_kernel<<<(9 * 128 * 64 + 255) / 256, 256>>>(conv_w);
    prep_data_kernel<<<dim3(34, F_TOT), 256>>>(data);
    conv_kernel<<<GRID, 512, CONV_SMEM>>>(conv_b);
    att_kernel<<<1, F_TOT>>>(mlp_w1, mlp_w2);
    lif_kernel<<<(B_SZ * CH * HW) / 256, 256>>>(out);
}